// round 13
// baseline (speedup 1.0000x reference)
#include <cuda_runtime.h>
#include <cuda_bf16.h>
#include <cuda_fp16.h>
#include <cstdint>
#include <cstdio>

#define N_NODES 32768
#define N_EDGES 32768
#define ND 12
#define ED 5
#define GD 11
#define H 64
#define T_OUT 4
#define STEPS 3

// ---------------- device scratch ----------------
__device__ __half g_ewh[(size_t)N_EDGES * H * H];  // 256 MB [e][h*64+o]
__device__ float g_h0[(size_t)N_NODES * H];
__device__ float g_h1[(size_t)N_NODES * H];
__device__ __align__(256) __half g_hs[(size_t)N_NODES * 128];  // h split [hi|lo]
__device__ float g_agg[(size_t)N_NODES * H];
__device__ __align__(256) __half g_a[(size_t)N_EDGES * 128];   // rf split [hi|lo]
__device__ __align__(256) __half g_b[(size_t)4096 * 128];      // We2 split [hi|hi]
__device__ __align__(256) __half g_gB1[256 * 128]; // [Whh rows | root^T rows], dup hi
__device__ __align__(256) __half g_gB2[192 * 128]; // Wih rows, dup hi
__device__ float g_w1T[133 * 64];
__device__ float g_w2T[64 * 32];
__device__ int   g_cnt[N_NODES];
__device__ int   g_src[N_EDGES];
__device__ int   g_dst[N_EDGES];
__device__ int   g_is64;

// ---------------- fused init ----------------
__global__ void init_kernel(const long long* ei, const float* __restrict__ Whh,
                            const float* __restrict__ root_, const float* __restrict__ Wih,
                            const float* __restrict__ Wd1, const float* __restrict__ Wd2,
                            const float* __restrict__ We2) {
    int gid = blockIdx.x * 256 + threadIdx.x;
    if (blockIdx.x == 0 && threadIdx.x < 32) {
        int l = threadIdx.x, ok = 1;
#pragma unroll
        for (int q = 0; q < 4; q++) {
            long long v = ei[l + q * 32];
            if (v < 0 || v >= N_NODES) ok = 0;
        }
        int all = __all_sync(0xffffffffu, ok);
        if (l == 0) g_is64 = all;
    }
    if (gid < N_NODES) g_cnt[gid] = 0;
    if (gid < N_NODES * H / 4) ((float4*)g_agg)[gid] = make_float4(0.f, 0.f, 0.f, 0.f);
    if (gid < 256 * 128) {
        int j = gid >> 7, kk = gid & 63;   // hi duplication across halves
        float v = (j < 192) ? Whh[j * 64 + kk] : root_[kk * 64 + (j - 192)];
        g_gB1[gid] = __float2half_rn(v);
    }
    if (gid < 192 * 128) {
        int j = gid >> 7, kk = gid & 63;
        g_gB2[gid] = __float2half_rn(Wih[j * 64 + kk]);
    }
    if (gid < 8512) {
        int o = gid / 133, c = gid % 133;
        g_w1T[c * 64 + o] = Wd1[gid];
    }
    if (gid < 2048) {
        int j = gid >> 6, o = gid & 63;
        g_w2T[o * 32 + j] = Wd2[gid];
    }
    if (gid < 4096 * 64) {
        int j = gid >> 6, k = gid & 63;
        __half hi = __float2half_rn(We2[gid]);
        size_t base = (size_t)j * 128;
        g_b[base + k] = hi;
        g_b[base + 64 + k] = hi;
    }
}

// ---------------- convert idx + count ----------------
__global__ void conv_count_kernel(const void* ei) {
    int i = blockIdx.x * blockDim.x + threadIdx.x;
    if (i >= N_EDGES) return;
    int s, d;
    if (g_is64) {
        const long long* p = (const long long*)ei;
        s = (int)p[i]; d = (int)p[N_EDGES + i];
    } else {
        const int* p = (const int*)ei;
        s = p[i]; d = p[N_EDGES + i];
    }
    g_src[i] = s; g_dst[i] = d;
    atomicAdd(&g_cnt[d], 1);
}

// ---------------- h init (+ split), 4 nodes/block, x staged ----------------
__global__ void hinit_kernel(const float* __restrict__ x, const float* __restrict__ u,
                             const float* __restrict__ Wp, const float* __restrict__ bp) {
    __shared__ float sW[H * (ND + GD)];
    __shared__ float sb[H];
    __shared__ float su[GD];
    __shared__ float sx[4 * ND];
    int t = threadIdx.x;
    for (int i = t; i < H * (ND + GD); i += 256) sW[i] = Wp[i];
    if (t < H) sb[t] = bp[t];
    if (t < GD) su[t] = u[t];
    if (t < 4 * ND) sx[t] = x[(size_t)blockIdx.x * 4 * ND + t];
    __syncthreads();
    int node = blockIdx.x * 4 + (t >> 6);
    int o = t & 63;
    const float* xr = sx + (t >> 6) * ND;
    const float* w = sW + o * (ND + GD);
    float acc = sb[o];
#pragma unroll
    for (int i = 0; i < ND; i++) acc += xr[i] * w[i];
#pragma unroll
    for (int i = 0; i < GD; i++) acc += su[i] * w[ND + i];
    float v = tanhf(acc);
    g_h0[(size_t)node * H + o] = v;
    __half hi = __float2half_rn(v);
    g_hs[(size_t)node * 128 + o] = hi;
    g_hs[(size_t)node * 128 + 64 + o] = __float2half_rn(v - __half2float(hi));
}

// ---------------- rfeat + split fused, 4 edges/block, ea staged ----------------
__global__ void rfeat_kernel(const float* __restrict__ ea, const float* __restrict__ We1,
                             const float* __restrict__ be1) {
    __shared__ float sW[H * ED];
    __shared__ float sb[H];
    __shared__ float se[4 * ED];
    int t = threadIdx.x;
    for (int i = t; i < H * ED; i += 256) sW[i] = We1[i];
    if (t < H) sb[t] = be1[t];
    if (t < 4 * ED) se[t] = ea[(size_t)blockIdx.x * 4 * ED + t];
    __syncthreads();
    int e = blockIdx.x * 4 + (t >> 6);
    int k = t & 63;
    const float* er = se + (t >> 6) * ED;
    float acc = sb[k];
#pragma unroll
    for (int i = 0; i < ED; i++) acc += er[i] * sW[k * ED + i];
    float v = fmaxf(acc, 0.0f);
    __half hi = __float2half_rn(v);
    g_a[(size_t)e * 128 + k] = hi;
    g_a[(size_t)e * 128 + 64 + k] = __float2half_rn(v - __half2float(hi));
}

// ---------------- mma helper ----------------
__device__ __forceinline__ void mma16816(float* c, const uint32_t* a, const uint32_t* b) {
    asm volatile(
        "mma.sync.aligned.m16n8k16.row.col.f32.f16.f16.f32 "
        "{%0,%1,%2,%3}, {%4,%5,%6,%7}, {%8,%9}, {%0,%1,%2,%3};"
        : "+f"(c[0]), "+f"(c[1]), "+f"(c[2]), "+f"(c[3])
        : "r"(a[0]), "r"(a[1]), "r"(a[2]), "r"(a[3]), "r"(b[0]), "r"(b[1]));
}

// ---------------- ew GEMM (verified) ----------------
#define GEMM_SMEM (2 * 128 * 68 * 4)

__global__ __launch_bounds__(256) void ewgemm_kernel(const float* __restrict__ be2) {
    extern __shared__ uint32_t sw[];
    uint32_t* As = sw;
    uint32_t* Bs = sw + 128 * 68;
    const int t = threadIdx.x;
    const int jb = blockIdx.x * 128;
    const int eb = blockIdx.y * 128;

    {
        int row = t >> 1, half = t & 1;
        const uint4* asrc = (const uint4*)(g_a + (size_t)(eb + row) * 128) + half * 8;
        const uint4* bsrc = (const uint4*)(g_b + (size_t)(jb + row) * 128) + half * 8;
        uint4* adst = (uint4*)(As + row * 68) + half * 8;
        uint4* bdst = (uint4*)(Bs + row * 68) + half * 8;
#pragma unroll
        for (int q = 0; q < 8; q++) { adst[q] = asrc[q]; bdst[q] = bsrc[q]; }
    }
    __syncthreads();

    const int wid = t >> 5, lane = t & 31;
    const int wm = wid & 3, wn = wid >> 2;
    const int g = lane >> 2, t4 = lane & 3;

    float acc[2][8][4];
#pragma unroll
    for (int mi = 0; mi < 2; mi++)
#pragma unroll
        for (int ni = 0; ni < 8; ni++)
#pragma unroll
            for (int q = 0; q < 4; q++) acc[mi][ni][q] = 0.0f;

    const uint32_t* Aw = As + (wm * 32 + g) * 68;
    const uint32_t* Bw = Bs + (wn * 64 + g) * 68;
#pragma unroll
    for (int ks = 0; ks < 8; ks++) {
        const int idx0 = ks * 8 + t4;
        uint32_t a[2][4], b[8][2];
#pragma unroll
        for (int mi = 0; mi < 2; mi++) {
            const uint32_t* p = Aw + mi * 16 * 68;
            a[mi][0] = p[idx0];
            a[mi][1] = p[8 * 68 + idx0];
            a[mi][2] = p[idx0 + 4];
            a[mi][3] = p[8 * 68 + idx0 + 4];
        }
#pragma unroll
        for (int ni = 0; ni < 8; ni++) {
            const uint32_t* p = Bw + ni * 8 * 68;
            b[ni][0] = p[idx0];
            b[ni][1] = p[idx0 + 4];
        }
#pragma unroll
        for (int mi = 0; mi < 2; mi++)
#pragma unroll
            for (int ni = 0; ni < 8; ni++)
                mma16816(acc[mi][ni], a[mi], b[ni]);
    }

#pragma unroll
    for (int ni = 0; ni < 8; ni++) {
        int col = jb + wn * 64 + ni * 8 + 2 * t4;
        float2 bb = *(const float2*)&be2[col];
#pragma unroll
        for (int mi = 0; mi < 2; mi++) {
            int row = eb + wm * 32 + mi * 16 + g;
            __half2 v0 = __floats2half2_rn(acc[mi][ni][0] + bb.x, acc[mi][ni][1] + bb.y);
            __half2 v1 = __floats2half2_rn(acc[mi][ni][2] + bb.x, acc[mi][ni][3] + bb.y);
            *(__half2*)(g_ewh + (size_t)row * 4096 + col) = v0;
            *(__half2*)(g_ewh + (size_t)(row + 8) * 4096 + col) = v1;
        }
    }
}

// ---------------- per step: msg + scatter-add (uint4 loads, shfl reduce) ----------------
__global__ __launch_bounds__(512) void msg_kernel(int parity) {
    const float* hin = parity ? g_h1 : g_h0;
    __shared__ float sh[16][64];
    int w = threadIdx.x >> 5, l = threadIdx.x & 31;
    int e = blockIdx.x * 16 + w;
    int s = g_src[e], d = g_dst[e];
    sh[w][l] = hin[(size_t)s * H + l];
    sh[w][l + 32] = hin[(size_t)s * H + l + 32];
    __syncwarp();

    const int lsub = l & 7;     // o-octet: o in [lsub*8, lsub*8+8)
    const int lh = l >> 3;      // h phase 0..3
    float acc[8];
#pragma unroll
    for (int j = 0; j < 8; j++) acc[j] = 0.0f;

    const char* base = (const char*)(g_ewh + (size_t)e * 4096) + lsub * 16;
#pragma unroll
    for (int it = 0; it < 16; it++) {
        int hh = it * 4 + lh;
        uint4 v = *(const uint4*)(base + hh * 128);
        const __half2* hp = (const __half2*)&v;
        float hv = sh[w][hh];
        float2 f0 = __half22float2(hp[0]);
        float2 f1 = __half22float2(hp[1]);
        float2 f2 = __half22float2(hp[2]);
        float2 f3 = __half22float2(hp[3]);
        acc[0] += hv * f0.x; acc[1] += hv * f0.y;
        acc[2] += hv * f1.x; acc[3] += hv * f1.y;
        acc[4] += hv * f2.x; acc[5] += hv * f2.y;
        acc[6] += hv * f3.x; acc[7] += hv * f3.y;
    }
    // reduce across the 4 h-phases (lanes lsub, lsub+8, lsub+16, lsub+24)
#pragma unroll
    for (int j = 0; j < 8; j++) {
        acc[j] += __shfl_xor_sync(0xffffffffu, acc[j], 8);
        acc[j] += __shfl_xor_sync(0xffffffffu, acc[j], 16);
    }
    if (l < 8) {
        float* dst = g_agg + (size_t)d * H + l * 8;
#pragma unroll
        for (int j = 0; j < 8; j++) atomicAdd(dst + j, acc[j]);
    }
}

// ---------------- per step: fully-fused tensor GRU ----------------
// smem layout (u32 offsets), 512 threads, 128 nodes/block:
//   phase1 : As @0 (8704) | Bs1 @8704 (17408)
//   phase2 : s_gh @0 stride 196 | s_hroot @25088 stride 68 | Bs2 @33792 | Am @46848
//   phase3 : s_gi @25088 stride 196
//   bias   : @55552 (448)
#define GRU_SMEM (56000 * 4)

__device__ __forceinline__ float sigf(float x) { return 1.0f / (1.0f + expf(-x)); }

__global__ __launch_bounds__(512) void gru_fused_kernel(int parity,
        const float* __restrict__ bih, const float* __restrict__ bhh,
        const float* __restrict__ conv_b) {
    const float* hin = parity ? g_h1 : g_h0;
    float* hout = parity ? g_h0 : g_h1;
    extern __shared__ uint32_t sw[];
    uint32_t* As    = sw;
    uint32_t* Bs1   = sw + 8704;
    float* s_gh     = (float*)sw;            // stride 196
    float* s_hroot  = (float*)(sw + 25088);  // stride 68
    uint32_t* Bs2   = sw + 33792;
    uint32_t* Am    = sw + 46848;
    float* s_gi     = (float*)(sw + 25088);  // stride 196, phase 3
    float* s_bias   = (float*)(sw + 55552);

    const int t = threadIdx.x;
    const int eb = blockIdx.x * 128;
    const int wid = t >> 5, lane = t & 31;
    const int wm = wid & 3, wn = wid >> 2;
    const int g = lane >> 2, t4 = lane & 3;

    if (t < 192) { s_bias[t] = bih[t]; s_bias[192 + t] = bhh[t]; }
    if (t >= 192 && t < 256) s_bias[384 + (t - 192)] = conv_b[t - 192];

    for (int i = t; i < 128 * 16; i += 512) {
        int row = i >> 4, q = i & 15;
        ((uint4*)(As + row * 68))[q] = ((const uint4*)(g_hs + (size_t)(eb + row) * 128))[q];
    }
    for (int i = t; i < 256 * 16; i += 512) {
        int row = i >> 4, q = i & 15;
        ((uint4*)(Bs1 + row * 68))[q] = ((const uint4*)(g_gB1 + (size_t)row * 128))[q];
    }
    __syncthreads();

    float acc[2][8][4];
#pragma unroll
    for (int mi = 0; mi < 2; mi++)
#pragma unroll
        for (int ni = 0; ni < 8; ni++)
#pragma unroll
            for (int q = 0; q < 4; q++) acc[mi][ni][q] = 0.0f;
    {
        const uint32_t* Aw = As + (wm * 32 + g) * 68;
        const uint32_t* Bw = Bs1 + (wn * 64 + g) * 68;
#pragma unroll
        for (int ks = 0; ks < 8; ks++) {
            const int idx0 = ks * 8 + t4;
            uint32_t a[2][4], b[8][2];
#pragma unroll
            for (int mi = 0; mi < 2; mi++) {
                const uint32_t* p = Aw + mi * 16 * 68;
                a[mi][0] = p[idx0];
                a[mi][1] = p[8 * 68 + idx0];
                a[mi][2] = p[idx0 + 4];
                a[mi][3] = p[8 * 68 + idx0 + 4];
            }
#pragma unroll
            for (int ni = 0; ni < 8; ni++) {
                const uint32_t* p = Bw + ni * 8 * 68;
                b[ni][0] = p[idx0];
                b[ni][1] = p[idx0 + 4];
            }
#pragma unroll
            for (int mi = 0; mi < 2; mi++)
#pragma unroll
                for (int ni = 0; ni < 8; ni++)
                    mma16816(acc[mi][ni], a[mi], b[ni]);
        }
    }
    __syncthreads();

#pragma unroll
    for (int ni = 0; ni < 8; ni++) {
        int col = wn * 64 + ni * 8 + 2 * t4;
#pragma unroll
        for (int mi = 0; mi < 2; mi++) {
            int row = wm * 32 + mi * 16 + g;
            if (wn < 3) {
                *(float2*)(s_gh + row * 196 + col) = make_float2(acc[mi][ni][0], acc[mi][ni][1]);
                *(float2*)(s_gh + (row + 8) * 196 + col) = make_float2(acc[mi][ni][2], acc[mi][ni][3]);
            } else {
                int hc = col - 192;
                *(float2*)(s_hroot + row * 68 + hc) = make_float2(acc[mi][ni][0], acc[mi][ni][1]);
                *(float2*)(s_hroot + (row + 8) * 68 + hc) = make_float2(acc[mi][ni][2], acc[mi][ni][3]);
            }
        }
    }
    __syncthreads();

    for (int i = t; i < 192 * 16; i += 512) {
        int row = i >> 4, q = i & 15;
        ((uint4*)(Bs2 + row * 68))[q] = ((const uint4*)(g_gB2 + (size_t)row * 128))[q];
    }
    {
        int r = t >> 2, q4 = t & 3;
        int node = eb + r;
        int cnt = g_cnt[node];
        float ic = 1.0f / (float)(cnt > 1 ? cnt : 1);
        float* aggp = g_agg + (size_t)node * 64;
        const float* ghr = s_hroot + r * 68;
#pragma unroll
        for (int q = 0; q < 4; q++) {
            int c = q4 * 16 + q * 4;
            float4 ag = *(float4*)(aggp + c);
            float4 hr = *(const float4*)(ghr + c);
            float4 cb4 = *(const float4*)(s_bias + 384 + c);
            *(float4*)(aggp + c) = make_float4(0.f, 0.f, 0.f, 0.f);
            float m0 = fmaxf(ag.x * ic + hr.x + cb4.x, 0.f);
            float m1 = fmaxf(ag.y * ic + hr.y + cb4.y, 0.f);
            float m2 = fmaxf(ag.z * ic + hr.z + cb4.z, 0.f);
            float m3 = fmaxf(ag.w * ic + hr.w + cb4.w, 0.f);
            __half h0 = __float2half_rn(m0), h1 = __float2half_rn(m1);
            __half h2 = __float2half_rn(m2), h3 = __float2half_rn(m3);
            __half2 hi01 = __halves2half2(h0, h1), hi23 = __halves2half2(h2, h3);
            __half2 lo01 = __halves2half2(__float2half_rn(m0 - __half2float(h0)),
                                          __float2half_rn(m1 - __half2float(h1)));
            __half2 lo23 = __halves2half2(__float2half_rn(m2 - __half2float(h2)),
                                          __float2half_rn(m3 - __half2float(h3)));
            Am[r * 68 + c / 2]          = *(uint32_t*)&hi01;
            Am[r * 68 + c / 2 + 1]      = *(uint32_t*)&hi23;
            Am[r * 68 + 32 + c / 2]     = *(uint32_t*)&lo01;
            Am[r * 68 + 32 + c / 2 + 1] = *(uint32_t*)&lo23;
        }
    }
    __syncthreads();

    float acc2[2][6][4];
#pragma unroll
    for (int mi = 0; mi < 2; mi++)
#pragma unroll
        for (int ni = 0; ni < 6; ni++)
#pragma unroll
            for (int q = 0; q < 4; q++) acc2[mi][ni][q] = 0.0f;
    {
        const uint32_t* Aw = Am + (wm * 32 + g) * 68;
        const uint32_t* Bw = Bs2 + (wn * 48 + g) * 68;
#pragma unroll
        for (int ks = 0; ks < 8; ks++) {
            const int idx0 = ks * 8 + t4;
            uint32_t a[2][4], b[6][2];
#pragma unroll
            for (int mi = 0; mi < 2; mi++) {
                const uint32_t* p = Aw + mi * 16 * 68;
                a[mi][0] = p[idx0];
                a[mi][1] = p[8 * 68 + idx0];
                a[mi][2] = p[idx0 + 4];
                a[mi][3] = p[8 * 68 + idx0 + 4];
            }
#pragma unroll
            for (int ni = 0; ni < 6; ni++) {
                const uint32_t* p = Bw + ni * 8 * 68;
                b[ni][0] = p[idx0];
                b[ni][1] = p[idx0 + 4];
            }
#pragma unroll
            for (int mi = 0; mi < 2; mi++)
#pragma unroll
                for (int ni = 0; ni < 6; ni++)
                    mma16816(acc2[mi][ni], a[mi], b[ni]);
        }
    }
    __syncthreads();

#pragma unroll
    for (int ni = 0; ni < 6; ni++) {
        int col = wn * 48 + ni * 8 + 2 * t4;
#pragma unroll
        for (int mi = 0; mi < 2; mi++) {
            int row = wm * 32 + mi * 16 + g;
            *(float2*)(s_gi + row * 196 + col) = make_float2(acc2[mi][ni][0], acc2[mi][ni][1]);
            *(float2*)(s_gi + (row + 8) * 196 + col) = make_float2(acc2[mi][ni][2], acc2[mi][ni][3]);
        }
    }
    __syncthreads();

    {
        int r = t >> 2, q4 = t & 3;
        int node = eb + r;
        const float* girow = s_gi + r * 196;
        const float* ghrow = s_gh + r * 196;
#pragma unroll
        for (int q = 0; q < 4; q++) {
            int c = q4 * 16 + q * 4;
            float4 gir = *(const float4*)(girow + c);
            float4 giz = *(const float4*)(girow + 64 + c);
            float4 gin = *(const float4*)(girow + 128 + c);
            float4 ghr = *(const float4*)(ghrow + c);
            float4 ghz = *(const float4*)(ghrow + 64 + c);
            float4 ghn = *(const float4*)(ghrow + 128 + c);
            float4 hv  = *(const float4*)(hin + (size_t)node * 64 + c);
            float4 bir = *(const float4*)(s_bias + c);
            float4 biz = *(const float4*)(s_bias + 64 + c);
            float4 bin = *(const float4*)(s_bias + 128 + c);
            float4 bhr = *(const float4*)(s_bias + 192 + c);
            float4 bhz = *(const float4*)(s_bias + 256 + c);
            float4 bhn = *(const float4*)(s_bias + 320 + c);
            float gr[4] = {gir.x + bir.x + ghr.x + bhr.x, gir.y + bir.y + ghr.y + bhr.y,
                           gir.z + bir.z + ghr.z + bhr.z, gir.w + bir.w + ghr.w + bhr.w};
            float gz[4] = {giz.x + biz.x + ghz.x + bhz.x, giz.y + biz.y + ghz.y + bhz.y,
                           giz.z + biz.z + ghz.z + bhz.z, giz.w + biz.w + ghz.w + bhz.w};
            float gni[4] = {gin.x + bin.x, gin.y + bin.y, gin.z + bin.z, gin.w + bin.w};
            float gnh[4] = {ghn.x + bhn.x, ghn.y + bhn.y, ghn.z + bhn.z, ghn.w + bhn.w};
            float hvv[4] = {hv.x, hv.y, hv.z, hv.w};
            float o_[4], lo_[4];
#pragma unroll
            for (int j = 0; j < 4; j++) {
                float rr = sigf(gr[j]);
                float zz = sigf(gz[j]);
                float nn = tanhf(gni[j] + rr * gnh[j]);
                o_[j] = (1.0f - zz) * nn + zz * hvv[j];
                __half hh = __float2half_rn(o_[j]);
                lo_[j] = o_[j] - __half2float(hh);
            }
            *(float4*)(hout + (size_t)node * 64 + c) = make_float4(o_[0], o_[1], o_[2], o_[3]);
            __half2* hsp = (__half2*)(g_hs + (size_t)node * 128 + c);
            hsp[0] = __floats2half2_rn(o_[0], o_[1]);
            hsp[1] = __floats2half2_rn(o_[2], o_[3]);
            __half2* lsp = (__half2*)(g_hs + (size_t)node * 128 + 64 + c);
            lsp[0] = __floats2half2_rn(lo_[0], lo_[1]);
            lsp[1] = __floats2half2_rn(lo_[2], lo_[3]);
        }
    }
}

// ---------------- decoder ----------------
__global__ __launch_bounds__(256) void decoder_kernel(int parity,
        const float* __restrict__ ea,
        const float* __restrict__ bd1, const float* __restrict__ bd2,
        const float* __restrict__ Wd3, const float* __restrict__ bd3,
        float* __restrict__ out) {
    const float* hin = parity ? g_h1 : g_h0;
    extern __shared__ float sm[];
    float* s_w1 = sm;
    float* s_w2 = s_w1 + 133 * 64;
    float* s_w3 = s_w2 + 64 * 32;
    float* s_b1 = s_w3 + 128;
    float* s_b2 = s_b1 + 64;
    float* s_b3 = s_b2 + 32;
    float* s_in = s_b3 + 4;
    float* s_d1 = s_in + 8 * 136;
    float* s_d2 = s_d1 + 8 * 64;

    int t = threadIdx.x;
    for (int i = t; i < 133 * 64; i += 256) s_w1[i] = g_w1T[i];
    for (int i = t; i < 64 * 32; i += 256) s_w2[i] = g_w2T[i];
    if (t < 128) s_w3[t] = Wd3[t];
    if (t < 64) s_b1[t] = bd1[t];
    if (t < 32) s_b2[t] = bd2[t];
    if (t < 4)  s_b3[t] = bd3[t];
    __syncthreads();

    int w = t >> 5, l = t & 31;

    for (int it = 0; it < 8; it++) {
        int e = blockIdx.x * 64 + it * 8 + w;
        int s = g_src[e], d = g_dst[e];
        s_in[w * 136 + l]      = hin[(size_t)s * H + l];
        s_in[w * 136 + l + 32] = hin[(size_t)s * H + l + 32];
        s_in[w * 136 + 64 + l]      = hin[(size_t)d * H + l];
        s_in[w * 136 + 64 + l + 32] = hin[(size_t)d * H + l + 32];
        if (l < ED) s_in[w * 136 + 128 + l] = ea[(size_t)e * ED + l];
        __syncwarp();

        float a0 = s_b1[l], a1 = s_b1[l + 32];
        for (int i = 0; i < 133; i++) {
            float v = s_in[w * 136 + i];
            a0 += v * s_w1[i * 64 + l];
            a1 += v * s_w1[i * 64 + l + 32];
        }
        s_d1[w * 64 + l] = fmaxf(a0, 0.0f);
        s_d1[w * 64 + l + 32] = fmaxf(a1, 0.0f);
        __syncwarp();

        float a2 = s_b2[l];
        for (int o = 0; o < 64; o++) a2 += s_d1[w * 64 + o] * s_w2[o * 32 + l];
        s_d2[w * 32 + l] = fmaxf(a2, 0.0f);
        __syncwarp();

        if (l < T_OUT) {
            float a3 = s_b3[l];
            for (int j = 0; j < 32; j++) a3 += s_d2[w * 32 + j] * s_w3[l * 32 + j];
            out[(size_t)e * T_OUT + l] = a3;
        }
        __syncwarp();
    }
}

#define DEC_SMEM  ((133*64 + 64*32 + 128 + 64 + 32 + 4 + 8*136 + 8*64 + 8*32) * 4)

static void set_attrs() {
    cudaFuncSetAttribute(ewgemm_kernel, cudaFuncAttributeMaxDynamicSharedMemorySize, GEMM_SMEM);
    cudaFuncSetAttribute(gru_fused_kernel, cudaFuncAttributeMaxDynamicSharedMemorySize, GRU_SMEM);
    cudaFuncSetAttribute(decoder_kernel, cudaFuncAttributeMaxDynamicSharedMemorySize, DEC_SMEM);
}

namespace { struct WarmLoad { WarmLoad() { set_attrs(); } } s_warm; }

extern "C" void kernel_launch(void* const* d_in, const int* in_sizes, int n_in,
                              void* d_out, int out_size) {
    (void)in_sizes; (void)n_in; (void)out_size;
    const float* x   = (const float*)d_in[0];
    const void*  ei  = d_in[1];
    const float* ea  = (const float*)d_in[2];
    const float* u   = (const float*)d_in[3];
    const float* Wp  = (const float*)d_in[4];
    const float* bp  = (const float*)d_in[5];
    const float* We1 = (const float*)d_in[6];
    const float* be1 = (const float*)d_in[7];
    const float* We2 = (const float*)d_in[8];
    const float* be2 = (const float*)d_in[9];
    const float* root = (const float*)d_in[10];
    const float* cb   = (const float*)d_in[11];
    const float* Wih = (const float*)d_in[12];
    const float* bih = (const float*)d_in[13];
    const float* Whh = (const float*)d_in[14];
    const float* bhh = (const float*)d_in[15];
    const float* Wd1 = (const float*)d_in[16];
    const float* bd1 = (const float*)d_in[17];
    const float* Wd2 = (const float*)d_in[18];
    const float* bd2 = (const float*)d_in[19];
    const float* Wd3 = (const float*)d_in[20];
    const float* bd3 = (const float*)d_in[21];
    float* out = (float*)d_out;

    set_attrs();

    init_kernel<<<N_NODES * H / 4 / 256, 256>>>((const long long*)ei, Whh, root, Wih, Wd1, Wd2, We2);
    conv_count_kernel<<<N_EDGES / 256, 256>>>(ei);
    hinit_kernel<<<N_NODES / 4, 256>>>(x, u, Wp, bp);
    rfeat_kernel<<<N_EDGES / 4, 256>>>(ea, We1, be1);

    {
        dim3 grid(4096 / 128, N_EDGES / 128);
        ewgemm_kernel<<<grid, 256, GEMM_SMEM>>>(be2);
    }

    for (int s = 0; s < STEPS; s++) {
        int parity = s & 1;
        msg_kernel<<<N_EDGES / 16, 512>>>(parity);
        gru_fused_kernel<<<N_NODES / 128, 512, GRU_SMEM>>>(parity, bih, bhh, cb);
    }

    decoder_kernel<<<N_EDGES / 64, 256, DEC_SMEM>>>(1, ea, bd1, bd2, Wd3, bd3, out);
}

// round 14
// speedup vs baseline: 1.0264x; 1.0264x over previous
#include <cuda_runtime.h>
#include <cuda_bf16.h>
#include <cuda_fp16.h>
#include <cstdint>
#include <cstdio>

#define N_NODES 32768
#define N_EDGES 32768
#define ND 12
#define ED 5
#define GD 11
#define H 64
#define T_OUT 4
#define STEPS 3

// ---------------- device scratch ----------------
__device__ __half g_ewh[(size_t)N_EDGES * H * H];  // 256 MB [e][h*64+o]
__device__ float g_h0[(size_t)N_NODES * H];
__device__ float g_h1[(size_t)N_NODES * H];
__device__ __align__(256) __half g_hs[(size_t)N_NODES * 128];  // h split [hi|lo]
__device__ float g_agg[(size_t)N_NODES * H];
__device__ __align__(256) __half g_a[(size_t)N_EDGES * 128];   // rf split [hi|lo]
__device__ __align__(256) __half g_b[(size_t)4096 * 128];      // We2 split [hi|hi]
__device__ __align__(256) __half g_gB1[256 * 128]; // [Whh rows | root^T rows], dup hi
__device__ __align__(256) __half g_gB2[192 * 128]; // Wih rows, dup hi
__device__ float g_w1T[133 * 64];
__device__ float g_w2T[64 * 32];
__device__ int   g_cnt[N_NODES];
__device__ int   g_src[N_EDGES];
__device__ int   g_dst[N_EDGES];
__device__ int   g_is64;

// ---------------- fused init ----------------
__global__ void init_kernel(const long long* ei, const float* __restrict__ Whh,
                            const float* __restrict__ root_, const float* __restrict__ Wih,
                            const float* __restrict__ Wd1, const float* __restrict__ Wd2,
                            const float* __restrict__ We2) {
    int gid = blockIdx.x * 256 + threadIdx.x;
    if (blockIdx.x == 0 && threadIdx.x < 32) {
        int l = threadIdx.x, ok = 1;
#pragma unroll
        for (int q = 0; q < 4; q++) {
            long long v = ei[l + q * 32];
            if (v < 0 || v >= N_NODES) ok = 0;
        }
        int all = __all_sync(0xffffffffu, ok);
        if (l == 0) g_is64 = all;
    }
    if (gid < N_NODES) g_cnt[gid] = 0;
    if (gid < N_NODES * H / 4) ((float4*)g_agg)[gid] = make_float4(0.f, 0.f, 0.f, 0.f);
    if (gid < 256 * 128) {
        int j = gid >> 7, kk = gid & 63;
        float v = (j < 192) ? Whh[j * 64 + kk] : root_[kk * 64 + (j - 192)];
        g_gB1[gid] = __float2half_rn(v);
    }
    if (gid < 192 * 128) {
        int j = gid >> 7, kk = gid & 63;
        g_gB2[gid] = __float2half_rn(Wih[j * 64 + kk]);
    }
    if (gid < 8512) {
        int o = gid / 133, c = gid % 133;
        g_w1T[c * 64 + o] = Wd1[gid];
    }
    if (gid < 2048) {
        int j = gid >> 6, o = gid & 63;
        g_w2T[o * 32 + j] = Wd2[gid];
    }
    if (gid < 4096 * 64) {
        int j = gid >> 6, k = gid & 63;
        __half hi = __float2half_rn(We2[gid]);
        size_t base = (size_t)j * 128;
        g_b[base + k] = hi;
        g_b[base + 64 + k] = hi;
    }
}

// ---------------- convert idx + count ----------------
__global__ void conv_count_kernel(const void* ei) {
    int i = blockIdx.x * blockDim.x + threadIdx.x;
    if (i >= N_EDGES) return;
    int s, d;
    if (g_is64) {
        const long long* p = (const long long*)ei;
        s = (int)p[i]; d = (int)p[N_EDGES + i];
    } else {
        const int* p = (const int*)ei;
        s = p[i]; d = p[N_EDGES + i];
    }
    g_src[i] = s; g_dst[i] = d;
    atomicAdd(&g_cnt[d], 1);
}

// ---------------- h init (+ split), 16 nodes/block (4 chunks) ----------------
__global__ void hinit_kernel(const float* __restrict__ x, const float* __restrict__ u,
                             const float* __restrict__ Wp, const float* __restrict__ bp) {
    __shared__ float sW[H * (ND + GD)];
    __shared__ float sb[H];
    __shared__ float su[GD];
    __shared__ float sx[16 * ND];
    int t = threadIdx.x;
    for (int i = t; i < H * (ND + GD); i += 256) sW[i] = Wp[i];
    if (t < H) sb[t] = bp[t];
    if (t < GD) su[t] = u[t];
    if (t < 16 * ND) sx[t] = x[(size_t)blockIdx.x * 16 * ND + t];
    __syncthreads();
    int o = t & 63;
    const float* w = sW + o * (ND + GD);
    float ubase = 0.0f;
#pragma unroll
    for (int i = 0; i < GD; i++) ubase += su[i] * w[ND + i];
#pragma unroll
    for (int c = 0; c < 4; c++) {
        int li = c * 4 + (t >> 6);
        int node = blockIdx.x * 16 + li;
        const float* xr = sx + li * ND;
        float acc = sb[o] + ubase;
#pragma unroll
        for (int i = 0; i < ND; i++) acc += xr[i] * w[i];
        float v = tanhf(acc);
        g_h0[(size_t)node * H + o] = v;
        __half hi = __float2half_rn(v);
        g_hs[(size_t)node * 128 + o] = hi;
        g_hs[(size_t)node * 128 + 64 + o] = __float2half_rn(v - __half2float(hi));
    }
}

// ---------------- rfeat + split fused, 16 edges/block (4 chunks) ----------------
__global__ void rfeat_kernel(const float* __restrict__ ea, const float* __restrict__ We1,
                             const float* __restrict__ be1) {
    __shared__ float sW[H * ED];
    __shared__ float sb[H];
    __shared__ float se[16 * ED];
    int t = threadIdx.x;
    for (int i = t; i < H * ED; i += 256) sW[i] = We1[i];
    if (t < H) sb[t] = be1[t];
    if (t < 16 * ED) se[t] = ea[(size_t)blockIdx.x * 16 * ED + t];
    __syncthreads();
    int k = t & 63;
#pragma unroll
    for (int c = 0; c < 4; c++) {
        int li = c * 4 + (t >> 6);
        int e = blockIdx.x * 16 + li;
        const float* er = se + li * ED;
        float acc = sb[k];
#pragma unroll
        for (int i = 0; i < ED; i++) acc += er[i] * sW[k * ED + i];
        float v = fmaxf(acc, 0.0f);
        __half hi = __float2half_rn(v);
        g_a[(size_t)e * 128 + k] = hi;
        g_a[(size_t)e * 128 + 64 + k] = __float2half_rn(v - __half2float(hi));
    }
}

// ---------------- mma helper ----------------
__device__ __forceinline__ void mma16816(float* c, const uint32_t* a, const uint32_t* b) {
    asm volatile(
        "mma.sync.aligned.m16n8k16.row.col.f32.f16.f16.f32 "
        "{%0,%1,%2,%3}, {%4,%5,%6,%7}, {%8,%9}, {%0,%1,%2,%3};"
        : "+f"(c[0]), "+f"(c[1]), "+f"(c[2]), "+f"(c[3])
        : "r"(a[0]), "r"(a[1]), "r"(a[2]), "r"(a[3]), "r"(b[0]), "r"(b[1]));
}

// ---------------- ew GEMM (verified) ----------------
#define GEMM_SMEM (2 * 128 * 68 * 4)

__global__ __launch_bounds__(256) void ewgemm_kernel(const float* __restrict__ be2) {
    extern __shared__ uint32_t sw[];
    uint32_t* As = sw;
    uint32_t* Bs = sw + 128 * 68;
    const int t = threadIdx.x;
    const int jb = blockIdx.x * 128;
    const int eb = blockIdx.y * 128;

    {
        int row = t >> 1, half = t & 1;
        const uint4* asrc = (const uint4*)(g_a + (size_t)(eb + row) * 128) + half * 8;
        const uint4* bsrc = (const uint4*)(g_b + (size_t)(jb + row) * 128) + half * 8;
        uint4* adst = (uint4*)(As + row * 68) + half * 8;
        uint4* bdst = (uint4*)(Bs + row * 68) + half * 8;
#pragma unroll
        for (int q = 0; q < 8; q++) { adst[q] = asrc[q]; bdst[q] = bsrc[q]; }
    }
    __syncthreads();

    const int wid = t >> 5, lane = t & 31;
    const int wm = wid & 3, wn = wid >> 2;
    const int g = lane >> 2, t4 = lane & 3;

    float acc[2][8][4];
#pragma unroll
    for (int mi = 0; mi < 2; mi++)
#pragma unroll
        for (int ni = 0; ni < 8; ni++)
#pragma unroll
            for (int q = 0; q < 4; q++) acc[mi][ni][q] = 0.0f;

    const uint32_t* Aw = As + (wm * 32 + g) * 68;
    const uint32_t* Bw = Bs + (wn * 64 + g) * 68;
#pragma unroll
    for (int ks = 0; ks < 8; ks++) {
        const int idx0 = ks * 8 + t4;
        uint32_t a[2][4], b[8][2];
#pragma unroll
        for (int mi = 0; mi < 2; mi++) {
            const uint32_t* p = Aw + mi * 16 * 68;
            a[mi][0] = p[idx0];
            a[mi][1] = p[8 * 68 + idx0];
            a[mi][2] = p[idx0 + 4];
            a[mi][3] = p[8 * 68 + idx0 + 4];
        }
#pragma unroll
        for (int ni = 0; ni < 8; ni++) {
            const uint32_t* p = Bw + ni * 8 * 68;
            b[ni][0] = p[idx0];
            b[ni][1] = p[idx0 + 4];
        }
#pragma unroll
        for (int mi = 0; mi < 2; mi++)
#pragma unroll
            for (int ni = 0; ni < 8; ni++)
                mma16816(acc[mi][ni], a[mi], b[ni]);
    }

#pragma unroll
    for (int ni = 0; ni < 8; ni++) {
        int col = jb + wn * 64 + ni * 8 + 2 * t4;
        float2 bb = *(const float2*)&be2[col];
#pragma unroll
        for (int mi = 0; mi < 2; mi++) {
            int row = eb + wm * 32 + mi * 16 + g;
            __half2 v0 = __floats2half2_rn(acc[mi][ni][0] + bb.x, acc[mi][ni][1] + bb.y);
            __half2 v1 = __floats2half2_rn(acc[mi][ni][2] + bb.x, acc[mi][ni][3] + bb.y);
            *(__half2*)(g_ewh + (size_t)row * 4096 + col) = v0;
            *(__half2*)(g_ewh + (size_t)(row + 8) * 4096 + col) = v1;
        }
    }
}

// ---------------- per step: msg (uint4 loads, shfl reduce, spread atomics) ----------------
__global__ __launch_bounds__(512) void msg_kernel(int parity) {
    const float* hin = parity ? g_h1 : g_h0;
    __shared__ float sh[16][64];
    int w = threadIdx.x >> 5, l = threadIdx.x & 31;
    int e = blockIdx.x * 16 + w;
    int s = g_src[e], d = g_dst[e];
    sh[w][l] = hin[(size_t)s * H + l];
    sh[w][l + 32] = hin[(size_t)s * H + l + 32];
    __syncwarp();

    const int lsub = l & 7;     // o-octet
    const int lh = l >> 3;      // h phase 0..3
    float acc[8];
#pragma unroll
    for (int j = 0; j < 8; j++) acc[j] = 0.0f;

    const char* base = (const char*)(g_ewh + (size_t)e * 4096) + lsub * 16;
#pragma unroll
    for (int it = 0; it < 16; it++) {
        int hh = it * 4 + lh;
        uint4 v = *(const uint4*)(base + hh * 128);
        const __half2* hp = (const __half2*)&v;
        float hv = sh[w][hh];
        float2 f0 = __half22float2(hp[0]);
        float2 f1 = __half22float2(hp[1]);
        float2 f2 = __half22float2(hp[2]);
        float2 f3 = __half22float2(hp[3]);
        acc[0] += hv * f0.x; acc[1] += hv * f0.y;
        acc[2] += hv * f1.x; acc[3] += hv * f1.y;
        acc[4] += hv * f2.x; acc[5] += hv * f2.y;
        acc[6] += hv * f3.x; acc[7] += hv * f3.y;
    }
#pragma unroll
    for (int j = 0; j < 8; j++) {
        acc[j] += __shfl_xor_sync(0xffffffffu, acc[j], 8);
        acc[j] += __shfl_xor_sync(0xffffffffu, acc[j], 16);
    }
    // all lanes hold full sums for their octet; lane lsub+8p writes elems 2p,2p+1
    {
        float* dst = g_agg + (size_t)d * H + lsub * 8 + 2 * lh;
        atomicAdd(dst, acc[2 * lh]);
        atomicAdd(dst + 1, acc[2 * lh + 1]);
    }
}

// ---------------- per step: fully-fused tensor GRU (verified R12) ----------------
#define GRU_SMEM (56000 * 4)

__device__ __forceinline__ float sigf(float x) { return 1.0f / (1.0f + expf(-x)); }

__global__ __launch_bounds__(512) void gru_fused_kernel(int parity,
        const float* __restrict__ bih, const float* __restrict__ bhh,
        const float* __restrict__ conv_b) {
    const float* hin = parity ? g_h1 : g_h0;
    float* hout = parity ? g_h0 : g_h1;
    extern __shared__ uint32_t sw[];
    uint32_t* As    = sw;
    uint32_t* Bs1   = sw + 8704;
    float* s_gh     = (float*)sw;            // stride 196
    float* s_hroot  = (float*)(sw + 25088);  // stride 68
    uint32_t* Bs2   = sw + 33792;
    uint32_t* Am    = sw + 46848;
    float* s_gi     = (float*)(sw + 25088);  // stride 196, phase 3
    float* s_bias   = (float*)(sw + 55552);

    const int t = threadIdx.x;
    const int eb = blockIdx.x * 128;
    const int wid = t >> 5, lane = t & 31;
    const int wm = wid & 3, wn = wid >> 2;
    const int g = lane >> 2, t4 = lane & 3;

    if (t < 192) { s_bias[t] = bih[t]; s_bias[192 + t] = bhh[t]; }
    if (t >= 192 && t < 256) s_bias[384 + (t - 192)] = conv_b[t - 192];

    for (int i = t; i < 128 * 16; i += 512) {
        int row = i >> 4, q = i & 15;
        ((uint4*)(As + row * 68))[q] = ((const uint4*)(g_hs + (size_t)(eb + row) * 128))[q];
    }
    for (int i = t; i < 256 * 16; i += 512) {
        int row = i >> 4, q = i & 15;
        ((uint4*)(Bs1 + row * 68))[q] = ((const uint4*)(g_gB1 + (size_t)row * 128))[q];
    }
    __syncthreads();

    float acc[2][8][4];
#pragma unroll
    for (int mi = 0; mi < 2; mi++)
#pragma unroll
        for (int ni = 0; ni < 8; ni++)
#pragma unroll
            for (int q = 0; q < 4; q++) acc[mi][ni][q] = 0.0f;
    {
        const uint32_t* Aw = As + (wm * 32 + g) * 68;
        const uint32_t* Bw = Bs1 + (wn * 64 + g) * 68;
#pragma unroll
        for (int ks = 0; ks < 8; ks++) {
            const int idx0 = ks * 8 + t4;
            uint32_t a[2][4], b[8][2];
#pragma unroll
            for (int mi = 0; mi < 2; mi++) {
                const uint32_t* p = Aw + mi * 16 * 68;
                a[mi][0] = p[idx0];
                a[mi][1] = p[8 * 68 + idx0];
                a[mi][2] = p[idx0 + 4];
                a[mi][3] = p[8 * 68 + idx0 + 4];
            }
#pragma unroll
            for (int ni = 0; ni < 8; ni++) {
                const uint32_t* p = Bw + ni * 8 * 68;
                b[ni][0] = p[idx0];
                b[ni][1] = p[idx0 + 4];
            }
#pragma unroll
            for (int mi = 0; mi < 2; mi++)
#pragma unroll
                for (int ni = 0; ni < 8; ni++)
                    mma16816(acc[mi][ni], a[mi], b[ni]);
        }
    }
    __syncthreads();

#pragma unroll
    for (int ni = 0; ni < 8; ni++) {
        int col = wn * 64 + ni * 8 + 2 * t4;
#pragma unroll
        for (int mi = 0; mi < 2; mi++) {
            int row = wm * 32 + mi * 16 + g;
            if (wn < 3) {
                *(float2*)(s_gh + row * 196 + col) = make_float2(acc[mi][ni][0], acc[mi][ni][1]);
                *(float2*)(s_gh + (row + 8) * 196 + col) = make_float2(acc[mi][ni][2], acc[mi][ni][3]);
            } else {
                int hc = col - 192;
                *(float2*)(s_hroot + row * 68 + hc) = make_float2(acc[mi][ni][0], acc[mi][ni][1]);
                *(float2*)(s_hroot + (row + 8) * 68 + hc) = make_float2(acc[mi][ni][2], acc[mi][ni][3]);
            }
        }
    }
    __syncthreads();

    for (int i = t; i < 192 * 16; i += 512) {
        int row = i >> 4, q = i & 15;
        ((uint4*)(Bs2 + row * 68))[q] = ((const uint4*)(g_gB2 + (size_t)row * 128))[q];
    }
    {
        int r = t >> 2, q4 = t & 3;
        int node = eb + r;
        int cnt = g_cnt[node];
        float ic = 1.0f / (float)(cnt > 1 ? cnt : 1);
        float* aggp = g_agg + (size_t)node * 64;
        const float* ghr = s_hroot + r * 68;
#pragma unroll
        for (int q = 0; q < 4; q++) {
            int c = q4 * 16 + q * 4;
            float4 ag = *(float4*)(aggp + c);
            float4 hr = *(const float4*)(ghr + c);
            float4 cb4 = *(const float4*)(s_bias + 384 + c);
            *(float4*)(aggp + c) = make_float4(0.f, 0.f, 0.f, 0.f);
            float m0 = fmaxf(ag.x * ic + hr.x + cb4.x, 0.f);
            float m1 = fmaxf(ag.y * ic + hr.y + cb4.y, 0.f);
            float m2 = fmaxf(ag.z * ic + hr.z + cb4.z, 0.f);
            float m3 = fmaxf(ag.w * ic + hr.w + cb4.w, 0.f);
            __half h0 = __float2half_rn(m0), h1 = __float2half_rn(m1);
            __half h2 = __float2half_rn(m2), h3 = __float2half_rn(m3);
            __half2 hi01 = __halves2half2(h0, h1), hi23 = __halves2half2(h2, h3);
            __half2 lo01 = __halves2half2(__float2half_rn(m0 - __half2float(h0)),
                                          __float2half_rn(m1 - __half2float(h1)));
            __half2 lo23 = __halves2half2(__float2half_rn(m2 - __half2float(h2)),
                                          __float2half_rn(m3 - __half2float(h3)));
            Am[r * 68 + c / 2]          = *(uint32_t*)&hi01;
            Am[r * 68 + c / 2 + 1]      = *(uint32_t*)&hi23;
            Am[r * 68 + 32 + c / 2]     = *(uint32_t*)&lo01;
            Am[r * 68 + 32 + c / 2 + 1] = *(uint32_t*)&lo23;
        }
    }
    __syncthreads();

    float acc2[2][6][4];
#pragma unroll
    for (int mi = 0; mi < 2; mi++)
#pragma unroll
        for (int ni = 0; ni < 6; ni++)
#pragma unroll
            for (int q = 0; q < 4; q++) acc2[mi][ni][q] = 0.0f;
    {
        const uint32_t* Aw = Am + (wm * 32 + g) * 68;
        const uint32_t* Bw = Bs2 + (wn * 48 + g) * 68;
#pragma unroll
        for (int ks = 0; ks < 8; ks++) {
            const int idx0 = ks * 8 + t4;
            uint32_t a[2][4], b[6][2];
#pragma unroll
            for (int mi = 0; mi < 2; mi++) {
                const uint32_t* p = Aw + mi * 16 * 68;
                a[mi][0] = p[idx0];
                a[mi][1] = p[8 * 68 + idx0];
                a[mi][2] = p[idx0 + 4];
                a[mi][3] = p[8 * 68 + idx0 + 4];
            }
#pragma unroll
            for (int ni = 0; ni < 6; ni++) {
                const uint32_t* p = Bw + ni * 8 * 68;
                b[ni][0] = p[idx0];
                b[ni][1] = p[idx0 + 4];
            }
#pragma unroll
            for (int mi = 0; mi < 2; mi++)
#pragma unroll
                for (int ni = 0; ni < 6; ni++)
                    mma16816(acc2[mi][ni], a[mi], b[ni]);
        }
    }
    __syncthreads();

#pragma unroll
    for (int ni = 0; ni < 6; ni++) {
        int col = wn * 48 + ni * 8 + 2 * t4;
#pragma unroll
        for (int mi = 0; mi < 2; mi++) {
            int row = wm * 32 + mi * 16 + g;
            *(float2*)(s_gi + row * 196 + col) = make_float2(acc2[mi][ni][0], acc2[mi][ni][1]);
            *(float2*)(s_gi + (row + 8) * 196 + col) = make_float2(acc2[mi][ni][2], acc2[mi][ni][3]);
        }
    }
    __syncthreads();

    {
        int r = t >> 2, q4 = t & 3;
        int node = eb + r;
        const float* girow = s_gi + r * 196;
        const float* ghrow = s_gh + r * 196;
#pragma unroll
        for (int q = 0; q < 4; q++) {
            int c = q4 * 16 + q * 4;
            float4 gir = *(const float4*)(girow + c);
            float4 giz = *(const float4*)(girow + 64 + c);
            float4 gin = *(const float4*)(girow + 128 + c);
            float4 ghr = *(const float4*)(ghrow + c);
            float4 ghz = *(const float4*)(ghrow + 64 + c);
            float4 ghn = *(const float4*)(ghrow + 128 + c);
            float4 hv  = *(const float4*)(hin + (size_t)node * 64 + c);
            float4 bir = *(const float4*)(s_bias + c);
            float4 biz = *(const float4*)(s_bias + 64 + c);
            float4 bin = *(const float4*)(s_bias + 128 + c);
            float4 bhr = *(const float4*)(s_bias + 192 + c);
            float4 bhz = *(const float4*)(s_bias + 256 + c);
            float4 bhn = *(const float4*)(s_bias + 320 + c);
            float gr[4] = {gir.x + bir.x + ghr.x + bhr.x, gir.y + bir.y + ghr.y + bhr.y,
                           gir.z + bir.z + ghr.z + bhr.z, gir.w + bir.w + ghr.w + bhr.w};
            float gz[4] = {giz.x + biz.x + ghz.x + bhz.x, giz.y + biz.y + ghz.y + bhz.y,
                           giz.z + biz.z + ghz.z + bhz.z, giz.w + biz.w + ghz.w + bhz.w};
            float gni[4] = {gin.x + bin.x, gin.y + bin.y, gin.z + bin.z, gin.w + bin.w};
            float gnh[4] = {ghn.x + bhn.x, ghn.y + bhn.y, ghn.z + bhn.z, ghn.w + bhn.w};
            float hvv[4] = {hv.x, hv.y, hv.z, hv.w};
            float o_[4], lo_[4];
#pragma unroll
            for (int j = 0; j < 4; j++) {
                float rr = sigf(gr[j]);
                float zz = sigf(gz[j]);
                float nn = tanhf(gni[j] + rr * gnh[j]);
                o_[j] = (1.0f - zz) * nn + zz * hvv[j];
                __half hh = __float2half_rn(o_[j]);
                lo_[j] = o_[j] - __half2float(hh);
            }
            *(float4*)(hout + (size_t)node * 64 + c) = make_float4(o_[0], o_[1], o_[2], o_[3]);
            __half2* hsp = (__half2*)(g_hs + (size_t)node * 128 + c);
            hsp[0] = __floats2half2_rn(o_[0], o_[1]);
            hsp[1] = __floats2half2_rn(o_[2], o_[3]);
            __half2* lsp = (__half2*)(g_hs + (size_t)node * 128 + 64 + c);
            lsp[0] = __floats2half2_rn(lo_[0], lo_[1]);
            lsp[1] = __floats2half2_rn(lo_[2], lo_[3]);
        }
    }
}

// ---------------- decoder ----------------
__global__ __launch_bounds__(256) void decoder_kernel(int parity,
        const float* __restrict__ ea,
        const float* __restrict__ bd1, const float* __restrict__ bd2,
        const float* __restrict__ Wd3, const float* __restrict__ bd3,
        float* __restrict__ out) {
    const float* hin = parity ? g_h1 : g_h0;
    extern __shared__ float sm[];
    float* s_w1 = sm;
    float* s_w2 = s_w1 + 133 * 64;
    float* s_w3 = s_w2 + 64 * 32;
    float* s_b1 = s_w3 + 128;
    float* s_b2 = s_b1 + 64;
    float* s_b3 = s_b2 + 32;
    float* s_in = s_b3 + 4;
    float* s_d1 = s_in + 8 * 136;
    float* s_d2 = s_d1 + 8 * 64;

    int t = threadIdx.x;
    for (int i = t; i < 133 * 64; i += 256) s_w1[i] = g_w1T[i];
    for (int i = t; i < 64 * 32; i += 256) s_w2[i] = g_w2T[i];
    if (t < 128) s_w3[t] = Wd3[t];
    if (t < 64) s_b1[t] = bd1[t];
    if (t < 32) s_b2[t] = bd2[t];
    if (t < 4)  s_b3[t] = bd3[t];
    __syncthreads();

    int w = t >> 5, l = t & 31;

    for (int it = 0; it < 8; it++) {
        int e = blockIdx.x * 64 + it * 8 + w;
        int s = g_src[e], d = g_dst[e];
        s_in[w * 136 + l]      = hin[(size_t)s * H + l];
        s_in[w * 136 + l + 32] = hin[(size_t)s * H + l + 32];
        s_in[w * 136 + 64 + l]      = hin[(size_t)d * H + l];
        s_in[w * 136 + 64 + l + 32] = hin[(size_t)d * H + l + 32];
        if (l < ED) s_in[w * 136 + 128 + l] = ea[(size_t)e * ED + l];
        __syncwarp();

        float a0 = s_b1[l], a1 = s_b1[l + 32];
        for (int i = 0; i < 133; i++) {
            float v = s_in[w * 136 + i];
            a0 += v * s_w1[i * 64 + l];
            a1 += v * s_w1[i * 64 + l + 32];
        }
        s_d1[w * 64 + l] = fmaxf(a0, 0.0f);
        s_d1[w * 64 + l + 32] = fmaxf(a1, 0.0f);
        __syncwarp();

        float a2 = s_b2[l];
        for (int o = 0; o < 64; o++) a2 += s_d1[w * 64 + o] * s_w2[o * 32 + l];
        s_d2[w * 32 + l] = fmaxf(a2, 0.0f);
        __syncwarp();

        if (l < T_OUT) {
            float a3 = s_b3[l];
            for (int j = 0; j < 32; j++) a3 += s_d2[w * 32 + j] * s_w3[l * 32 + j];
            out[(size_t)e * T_OUT + l] = a3;
        }
        __syncwarp();
    }
}

#define DEC_SMEM  ((133*64 + 64*32 + 128 + 64 + 32 + 4 + 8*136 + 8*64 + 8*32) * 4)

static void set_attrs() {
    cudaFuncSetAttribute(ewgemm_kernel, cudaFuncAttributeMaxDynamicSharedMemorySize, GEMM_SMEM);
    cudaFuncSetAttribute(gru_fused_kernel, cudaFuncAttributeMaxDynamicSharedMemorySize, GRU_SMEM);
    cudaFuncSetAttribute(decoder_kernel, cudaFuncAttributeMaxDynamicSharedMemorySize, DEC_SMEM);
}

namespace { struct WarmLoad { WarmLoad() { set_attrs(); } } s_warm; }

extern "C" void kernel_launch(void* const* d_in, const int* in_sizes, int n_in,
                              void* d_out, int out_size) {
    (void)in_sizes; (void)n_in; (void)out_size;
    const float* x   = (const float*)d_in[0];
    const void*  ei  = d_in[1];
    const float* ea  = (const float*)d_in[2];
    const float* u   = (const float*)d_in[3];
    const float* Wp  = (const float*)d_in[4];
    const float* bp  = (const float*)d_in[5];
    const float* We1 = (const float*)d_in[6];
    const float* be1 = (const float*)d_in[7];
    const float* We2 = (const float*)d_in[8];
    const float* be2 = (const float*)d_in[9];
    const float* root = (const float*)d_in[10];
    const float* cb   = (const float*)d_in[11];
    const float* Wih = (const float*)d_in[12];
    const float* bih = (const float*)d_in[13];
    const float* Whh = (const float*)d_in[14];
    const float* bhh = (const float*)d_in[15];
    const float* Wd1 = (const float*)d_in[16];
    const float* bd1 = (const float*)d_in[17];
    const float* Wd2 = (const float*)d_in[18];
    const float* bd2 = (const float*)d_in[19];
    const float* Wd3 = (const float*)d_in[20];
    const float* bd3 = (const float*)d_in[21];
    float* out = (float*)d_out;

    set_attrs();

    init_kernel<<<N_NODES * H / 4 / 256, 256>>>((const long long*)ei, Whh, root, Wih, Wd1, Wd2, We2);
    conv_count_kernel<<<N_EDGES / 256, 256>>>(ei);
    hinit_kernel<<<N_NODES / 16, 256>>>(x, u, Wp, bp);
    rfeat_kernel<<<N_EDGES / 16, 256>>>(ea, We1, be1);

    {
        dim3 grid(4096 / 128, N_EDGES / 128);
        ewgemm_kernel<<<grid, 256, GEMM_SMEM>>>(be2);
    }

    for (int s = 0; s < STEPS; s++) {
        int parity = s & 1;
        msg_kernel<<<N_EDGES / 16, 512>>>(parity);
        gru_fused_kernel<<<N_NODES / 128, 512, GRU_SMEM>>>(parity, bih, bhh, cb);
    }

    decoder_kernel<<<N_EDGES / 64, 256, DEC_SMEM>>>(1, ea, bd1, bd2, Wd3, bd3, out);
}

// round 15
// speedup vs baseline: 1.1906x; 1.1599x over previous
#include <cuda_runtime.h>
#include <cuda_bf16.h>
#include <cuda_fp16.h>
#include <cstdint>
#include <cstdio>

#define N_NODES 32768
#define N_EDGES 32768
#define ND 12
#define ED 5
#define GD 11
#define H 64
#define T_OUT 4
#define STEPS 3

// ---------------- device scratch ----------------
__device__ __half g_ewh[(size_t)N_EDGES * H * H];
__device__ float g_h0[(size_t)N_NODES * H];
__device__ float g_h1[(size_t)N_NODES * H];
__device__ __align__(256) __half g_hs[(size_t)N_NODES * 128];
__device__ float g_agg[(size_t)N_NODES * H];
__device__ __align__(256) __half g_a[(size_t)N_EDGES * 128];
__device__ __align__(256) __half g_b[(size_t)4096 * 128];
__device__ __align__(256) __half g_gB1[256 * 128];
__device__ __align__(256) __half g_gB2[192 * 128];
__device__ __align__(256) __half g_d1s[64 * 288];   // Wd1 split [hi144|lo144]
__device__ __align__(256) __half g_d2s[32 * 128];   // Wd2 split [hi64|lo64]
__device__ int   g_cnt[N_NODES];
__device__ int   g_src[N_EDGES];
__device__ int   g_dst[N_EDGES];
__device__ int   g_is64;

// ---------------- fused init ----------------
__global__ void init_kernel(const long long* ei, const float* __restrict__ Whh,
                            const float* __restrict__ root_, const float* __restrict__ Wih,
                            const float* __restrict__ Wd1, const float* __restrict__ Wd2,
                            const float* __restrict__ We2) {
    int gid = blockIdx.x * 256 + threadIdx.x;
    if (blockIdx.x == 0 && threadIdx.x < 32) {
        int l = threadIdx.x, ok = 1;
#pragma unroll
        for (int q = 0; q < 4; q++) {
            long long v = ei[l + q * 32];
            if (v < 0 || v >= N_NODES) ok = 0;
        }
        int all = __all_sync(0xffffffffu, ok);
        if (l == 0) g_is64 = all;
    }
    if (gid < N_NODES) g_cnt[gid] = 0;
    if (gid < N_NODES * H / 4) ((float4*)g_agg)[gid] = make_float4(0.f, 0.f, 0.f, 0.f);
    if (gid < 256 * 128) {
        int j = gid >> 7, kk = gid & 63;
        float v = (j < 192) ? Whh[j * 64 + kk] : root_[kk * 64 + (j - 192)];
        g_gB1[gid] = __float2half_rn(v);
    }
    if (gid < 192 * 128) {
        int j = gid >> 7, kk = gid & 63;
        g_gB2[gid] = __float2half_rn(Wih[j * 64 + kk]);
    }
    if (gid < 64 * 288) {
        int o = gid / 288, c = gid % 288;
        int cc = (c < 144) ? c : c - 144;
        float v = (cc < 133) ? Wd1[o * 133 + cc] : 0.0f;
        __half hi = __float2half_rn(v);
        g_d1s[gid] = (c < 144) ? hi : __float2half_rn(v - __half2float(hi));
    }
    if (gid < 32 * 128) {
        int o = gid >> 7, c = gid & 127;
        float v = Wd2[o * 64 + (c & 63)];
        __half hi = __float2half_rn(v);
        g_d2s[gid] = (c < 64) ? hi : __float2half_rn(v - __half2float(hi));
    }
    if (gid < 4096 * 64) {
        int j = gid >> 6, k = gid & 63;
        __half hi = __float2half_rn(We2[gid]);
        size_t base = (size_t)j * 128;
        g_b[base + k] = hi;
        g_b[base + 64 + k] = hi;
    }
}

// ---------------- convert idx + count ----------------
__global__ void conv_count_kernel(const void* ei) {
    int i = blockIdx.x * blockDim.x + threadIdx.x;
    if (i >= N_EDGES) return;
    int s, d;
    if (g_is64) {
        const long long* p = (const long long*)ei;
        s = (int)p[i]; d = (int)p[N_EDGES + i];
    } else {
        const int* p = (const int*)ei;
        s = p[i]; d = p[N_EDGES + i];
    }
    g_src[i] = s; g_dst[i] = d;
    atomicAdd(&g_cnt[d], 1);
}

// ---------------- h init (+ split), 16 nodes/block ----------------
__global__ void hinit_kernel(const float* __restrict__ x, const float* __restrict__ u,
                             const float* __restrict__ Wp, const float* __restrict__ bp) {
    __shared__ float sW[H * (ND + GD)];
    __shared__ float sb[H];
    __shared__ float su[GD];
    __shared__ float sx[16 * ND];
    int t = threadIdx.x;
    for (int i = t; i < H * (ND + GD); i += 256) sW[i] = Wp[i];
    if (t < H) sb[t] = bp[t];
    if (t < GD) su[t] = u[t];
    if (t < 16 * ND) sx[t] = x[(size_t)blockIdx.x * 16 * ND + t];
    __syncthreads();
    int o = t & 63;
    const float* w = sW + o * (ND + GD);
    float ubase = 0.0f;
#pragma unroll
    for (int i = 0; i < GD; i++) ubase += su[i] * w[ND + i];
#pragma unroll
    for (int c = 0; c < 4; c++) {
        int li = c * 4 + (t >> 6);
        int node = blockIdx.x * 16 + li;
        const float* xr = sx + li * ND;
        float acc = sb[o] + ubase;
#pragma unroll
        for (int i = 0; i < ND; i++) acc += xr[i] * w[i];
        float v = tanhf(acc);
        g_h0[(size_t)node * H + o] = v;
        __half hi = __float2half_rn(v);
        g_hs[(size_t)node * 128 + o] = hi;
        g_hs[(size_t)node * 128 + 64 + o] = __float2half_rn(v - __half2float(hi));
    }
}

// ---------------- rfeat + split, 16 edges/block ----------------
__global__ void rfeat_kernel(const float* __restrict__ ea, const float* __restrict__ We1,
                             const float* __restrict__ be1) {
    __shared__ float sW[H * ED];
    __shared__ float sb[H];
    __shared__ float se[16 * ED];
    int t = threadIdx.x;
    for (int i = t; i < H * ED; i += 256) sW[i] = We1[i];
    if (t < H) sb[t] = be1[t];
    if (t < 16 * ED) se[t] = ea[(size_t)blockIdx.x * 16 * ED + t];
    __syncthreads();
    int k = t & 63;
#pragma unroll
    for (int c = 0; c < 4; c++) {
        int li = c * 4 + (t >> 6);
        int e = blockIdx.x * 16 + li;
        const float* er = se + li * ED;
        float acc = sb[k];
#pragma unroll
        for (int i = 0; i < ED; i++) acc += er[i] * sW[k * ED + i];
        float v = fmaxf(acc, 0.0f);
        __half hi = __float2half_rn(v);
        g_a[(size_t)e * 128 + k] = hi;
        g_a[(size_t)e * 128 + 64 + k] = __float2half_rn(v - __half2float(hi));
    }
}

// ---------------- mma helper ----------------
__device__ __forceinline__ void mma16816(float* c, const uint32_t* a, const uint32_t* b) {
    asm volatile(
        "mma.sync.aligned.m16n8k16.row.col.f32.f16.f16.f32 "
        "{%0,%1,%2,%3}, {%4,%5,%6,%7}, {%8,%9}, {%0,%1,%2,%3};"
        : "+f"(c[0]), "+f"(c[1]), "+f"(c[2]), "+f"(c[3])
        : "r"(a[0]), "r"(a[1]), "r"(a[2]), "r"(a[3]), "r"(b[0]), "r"(b[1]));
}

// ---------------- ew GEMM (verified) ----------------
#define GEMM_SMEM (2 * 128 * 68 * 4)

__global__ __launch_bounds__(256) void ewgemm_kernel(const float* __restrict__ be2) {
    extern __shared__ uint32_t sw[];
    uint32_t* As = sw;
    uint32_t* Bs = sw + 128 * 68;
    const int t = threadIdx.x;
    const int jb = blockIdx.x * 128;
    const int eb = blockIdx.y * 128;

    {
        int row = t >> 1, half = t & 1;
        const uint4* asrc = (const uint4*)(g_a + (size_t)(eb + row) * 128) + half * 8;
        const uint4* bsrc = (const uint4*)(g_b + (size_t)(jb + row) * 128) + half * 8;
        uint4* adst = (uint4*)(As + row * 68) + half * 8;
        uint4* bdst = (uint4*)(Bs + row * 68) + half * 8;
#pragma unroll
        for (int q = 0; q < 8; q++) { adst[q] = asrc[q]; bdst[q] = bsrc[q]; }
    }
    __syncthreads();

    const int wid = t >> 5, lane = t & 31;
    const int wm = wid & 3, wn = wid >> 2;
    const int g = lane >> 2, t4 = lane & 3;

    float acc[2][8][4];
#pragma unroll
    for (int mi = 0; mi < 2; mi++)
#pragma unroll
        for (int ni = 0; ni < 8; ni++)
#pragma unroll
            for (int q = 0; q < 4; q++) acc[mi][ni][q] = 0.0f;

    const uint32_t* Aw = As + (wm * 32 + g) * 68;
    const uint32_t* Bw = Bs + (wn * 64 + g) * 68;
#pragma unroll
    for (int ks = 0; ks < 8; ks++) {
        const int idx0 = ks * 8 + t4;
        uint32_t a[2][4], b[8][2];
#pragma unroll
        for (int mi = 0; mi < 2; mi++) {
            const uint32_t* p = Aw + mi * 16 * 68;
            a[mi][0] = p[idx0];
            a[mi][1] = p[8 * 68 + idx0];
            a[mi][2] = p[idx0 + 4];
            a[mi][3] = p[8 * 68 + idx0 + 4];
        }
#pragma unroll
        for (int ni = 0; ni < 8; ni++) {
            const uint32_t* p = Bw + ni * 8 * 68;
            b[ni][0] = p[idx0];
            b[ni][1] = p[idx0 + 4];
        }
#pragma unroll
        for (int mi = 0; mi < 2; mi++)
#pragma unroll
            for (int ni = 0; ni < 8; ni++)
                mma16816(acc[mi][ni], a[mi], b[ni]);
    }

#pragma unroll
    for (int ni = 0; ni < 8; ni++) {
        int col = jb + wn * 64 + ni * 8 + 2 * t4;
        float2 bb = *(const float2*)&be2[col];
#pragma unroll
        for (int mi = 0; mi < 2; mi++) {
            int row = eb + wm * 32 + mi * 16 + g;
            __half2 v0 = __floats2half2_rn(acc[mi][ni][0] + bb.x, acc[mi][ni][1] + bb.y);
            __half2 v1 = __floats2half2_rn(acc[mi][ni][2] + bb.x, acc[mi][ni][3] + bb.y);
            *(__half2*)(g_ewh + (size_t)row * 4096 + col) = v0;
            *(__half2*)(g_ewh + (size_t)(row + 8) * 4096 + col) = v1;
        }
    }
}

// ---------------- per step: msg (uint4 streaming loads, shfl reduce) ----------------
__global__ __launch_bounds__(512) void msg_kernel(int parity) {
    const float* hin = parity ? g_h1 : g_h0;
    __shared__ float sh[16][64];
    int w = threadIdx.x >> 5, l = threadIdx.x & 31;
    int e = blockIdx.x * 16 + w;
    int s = g_src[e], d = g_dst[e];
    sh[w][l] = hin[(size_t)s * H + l];
    sh[w][l + 32] = hin[(size_t)s * H + l + 32];
    __syncwarp();

    const int lsub = l & 7;
    const int lh = l >> 3;
    float acc[8];
#pragma unroll
    for (int j = 0; j < 8; j++) acc[j] = 0.0f;

    const char* base = (const char*)(g_ewh + (size_t)e * 4096) + lsub * 16;
#pragma unroll
    for (int it = 0; it < 16; it++) {
        int hh = it * 4 + lh;
        uint4 v = __ldcs((const uint4*)(base + hh * 128));
        const __half2* hp = (const __half2*)&v;
        float hv = sh[w][hh];
        float2 f0 = __half22float2(hp[0]);
        float2 f1 = __half22float2(hp[1]);
        float2 f2 = __half22float2(hp[2]);
        float2 f3 = __half22float2(hp[3]);
        acc[0] += hv * f0.x; acc[1] += hv * f0.y;
        acc[2] += hv * f1.x; acc[3] += hv * f1.y;
        acc[4] += hv * f2.x; acc[5] += hv * f2.y;
        acc[6] += hv * f3.x; acc[7] += hv * f3.y;
    }
#pragma unroll
    for (int j = 0; j < 8; j++) {
        acc[j] += __shfl_xor_sync(0xffffffffu, acc[j], 8);
        acc[j] += __shfl_xor_sync(0xffffffffu, acc[j], 16);
    }
    {
        float* dst = g_agg + (size_t)d * H + lsub * 8 + 2 * lh;
        atomicAdd(dst, acc[2 * lh]);
        atomicAdd(dst + 1, acc[2 * lh + 1]);
    }
}

// ---------------- per step: fully-fused tensor GRU (verified R12) ----------------
#define GRU_SMEM (56000 * 4)

__device__ __forceinline__ float sigf(float x) { return 1.0f / (1.0f + expf(-x)); }

__global__ __launch_bounds__(512) void gru_fused_kernel(int parity,
        const float* __restrict__ bih, const float* __restrict__ bhh,
        const float* __restrict__ conv_b) {
    const float* hin = parity ? g_h1 : g_h0;
    float* hout = parity ? g_h0 : g_h1;
    extern __shared__ uint32_t sw[];
    uint32_t* As    = sw;
    uint32_t* Bs1   = sw + 8704;
    float* s_gh     = (float*)sw;
    float* s_hroot  = (float*)(sw + 25088);
    uint32_t* Bs2   = sw + 33792;
    uint32_t* Am    = sw + 46848;
    float* s_gi     = (float*)(sw + 25088);
    float* s_bias   = (float*)(sw + 55552);

    const int t = threadIdx.x;
    const int eb = blockIdx.x * 128;
    const int wid = t >> 5, lane = t & 31;
    const int wm = wid & 3, wn = wid >> 2;
    const int g = lane >> 2, t4 = lane & 3;

    if (t < 192) { s_bias[t] = bih[t]; s_bias[192 + t] = bhh[t]; }
    if (t >= 192 && t < 256) s_bias[384 + (t - 192)] = conv_b[t - 192];

    for (int i = t; i < 128 * 16; i += 512) {
        int row = i >> 4, q = i & 15;
        ((uint4*)(As + row * 68))[q] = ((const uint4*)(g_hs + (size_t)(eb + row) * 128))[q];
    }
    for (int i = t; i < 256 * 16; i += 512) {
        int row = i >> 4, q = i & 15;
        ((uint4*)(Bs1 + row * 68))[q] = ((const uint4*)(g_gB1 + (size_t)row * 128))[q];
    }
    __syncthreads();

    float acc[2][8][4];
#pragma unroll
    for (int mi = 0; mi < 2; mi++)
#pragma unroll
        for (int ni = 0; ni < 8; ni++)
#pragma unroll
            for (int q = 0; q < 4; q++) acc[mi][ni][q] = 0.0f;
    {
        const uint32_t* Aw = As + (wm * 32 + g) * 68;
        const uint32_t* Bw = Bs1 + (wn * 64 + g) * 68;
#pragma unroll
        for (int ks = 0; ks < 8; ks++) {
            const int idx0 = ks * 8 + t4;
            uint32_t a[2][4], b[8][2];
#pragma unroll
            for (int mi = 0; mi < 2; mi++) {
                const uint32_t* p = Aw + mi * 16 * 68;
                a[mi][0] = p[idx0];
                a[mi][1] = p[8 * 68 + idx0];
                a[mi][2] = p[idx0 + 4];
                a[mi][3] = p[8 * 68 + idx0 + 4];
            }
#pragma unroll
            for (int ni = 0; ni < 8; ni++) {
                const uint32_t* p = Bw + ni * 8 * 68;
                b[ni][0] = p[idx0];
                b[ni][1] = p[idx0 + 4];
            }
#pragma unroll
            for (int mi = 0; mi < 2; mi++)
#pragma unroll
                for (int ni = 0; ni < 8; ni++)
                    mma16816(acc[mi][ni], a[mi], b[ni]);
        }
    }
    __syncthreads();

#pragma unroll
    for (int ni = 0; ni < 8; ni++) {
        int col = wn * 64 + ni * 8 + 2 * t4;
#pragma unroll
        for (int mi = 0; mi < 2; mi++) {
            int row = wm * 32 + mi * 16 + g;
            if (wn < 3) {
                *(float2*)(s_gh + row * 196 + col) = make_float2(acc[mi][ni][0], acc[mi][ni][1]);
                *(float2*)(s_gh + (row + 8) * 196 + col) = make_float2(acc[mi][ni][2], acc[mi][ni][3]);
            } else {
                int hc = col - 192;
                *(float2*)(s_hroot + row * 68 + hc) = make_float2(acc[mi][ni][0], acc[mi][ni][1]);
                *(float2*)(s_hroot + (row + 8) * 68 + hc) = make_float2(acc[mi][ni][2], acc[mi][ni][3]);
            }
        }
    }
    __syncthreads();

    for (int i = t; i < 192 * 16; i += 512) {
        int row = i >> 4, q = i & 15;
        ((uint4*)(Bs2 + row * 68))[q] = ((const uint4*)(g_gB2 + (size_t)row * 128))[q];
    }
    {
        int r = t >> 2, q4 = t & 3;
        int node = eb + r;
        int cnt = g_cnt[node];
        float ic = 1.0f / (float)(cnt > 1 ? cnt : 1);
        float* aggp = g_agg + (size_t)node * 64;
        const float* ghr = s_hroot + r * 68;
#pragma unroll
        for (int q = 0; q < 4; q++) {
            int c = q4 * 16 + q * 4;
            float4 ag = *(float4*)(aggp + c);
            float4 hr = *(const float4*)(ghr + c);
            float4 cb4 = *(const float4*)(s_bias + 384 + c);
            *(float4*)(aggp + c) = make_float4(0.f, 0.f, 0.f, 0.f);
            float m0 = fmaxf(ag.x * ic + hr.x + cb4.x, 0.f);
            float m1 = fmaxf(ag.y * ic + hr.y + cb4.y, 0.f);
            float m2 = fmaxf(ag.z * ic + hr.z + cb4.z, 0.f);
            float m3 = fmaxf(ag.w * ic + hr.w + cb4.w, 0.f);
            __half h0 = __float2half_rn(m0), h1 = __float2half_rn(m1);
            __half h2 = __float2half_rn(m2), h3 = __float2half_rn(m3);
            __half2 hi01 = __halves2half2(h0, h1), hi23 = __halves2half2(h2, h3);
            __half2 lo01 = __halves2half2(__float2half_rn(m0 - __half2float(h0)),
                                          __float2half_rn(m1 - __half2float(h1)));
            __half2 lo23 = __halves2half2(__float2half_rn(m2 - __half2float(h2)),
                                          __float2half_rn(m3 - __half2float(h3)));
            Am[r * 68 + c / 2]          = *(uint32_t*)&hi01;
            Am[r * 68 + c / 2 + 1]      = *(uint32_t*)&hi23;
            Am[r * 68 + 32 + c / 2]     = *(uint32_t*)&lo01;
            Am[r * 68 + 32 + c / 2 + 1] = *(uint32_t*)&lo23;
        }
    }
    __syncthreads();

    float acc2[2][6][4];
#pragma unroll
    for (int mi = 0; mi < 2; mi++)
#pragma unroll
        for (int ni = 0; ni < 6; ni++)
#pragma unroll
            for (int q = 0; q < 4; q++) acc2[mi][ni][q] = 0.0f;
    {
        const uint32_t* Aw = Am + (wm * 32 + g) * 68;
        const uint32_t* Bw = Bs2 + (wn * 48 + g) * 68;
#pragma unroll
        for (int ks = 0; ks < 8; ks++) {
            const int idx0 = ks * 8 + t4;
            uint32_t a[2][4], b[6][2];
#pragma unroll
            for (int mi = 0; mi < 2; mi++) {
                const uint32_t* p = Aw + mi * 16 * 68;
                a[mi][0] = p[idx0];
                a[mi][1] = p[8 * 68 + idx0];
                a[mi][2] = p[idx0 + 4];
                a[mi][3] = p[8 * 68 + idx0 + 4];
            }
#pragma unroll
            for (int ni = 0; ni < 6; ni++) {
                const uint32_t* p = Bw + ni * 8 * 68;
                b[ni][0] = p[idx0];
                b[ni][1] = p[idx0 + 4];
            }
#pragma unroll
            for (int mi = 0; mi < 2; mi++)
#pragma unroll
                for (int ni = 0; ni < 6; ni++)
                    mma16816(acc2[mi][ni], a[mi], b[ni]);
        }
    }
    __syncthreads();

#pragma unroll
    for (int ni = 0; ni < 6; ni++) {
        int col = wn * 48 + ni * 8 + 2 * t4;
#pragma unroll
        for (int mi = 0; mi < 2; mi++) {
            int row = wm * 32 + mi * 16 + g;
            *(float2*)(s_gi + row * 196 + col) = make_float2(acc2[mi][ni][0], acc2[mi][ni][1]);
            *(float2*)(s_gi + (row + 8) * 196 + col) = make_float2(acc2[mi][ni][2], acc2[mi][ni][3]);
        }
    }
    __syncthreads();

    {
        int r = t >> 2, q4 = t & 3;
        int node = eb + r;
        const float* girow = s_gi + r * 196;
        const float* ghrow = s_gh + r * 196;
#pragma unroll
        for (int q = 0; q < 4; q++) {
            int c = q4 * 16 + q * 4;
            float4 gir = *(const float4*)(girow + c);
            float4 giz = *(const float4*)(girow + 64 + c);
            float4 gin = *(const float4*)(girow + 128 + c);
            float4 ghr = *(const float4*)(ghrow + c);
            float4 ghz = *(const float4*)(ghrow + 64 + c);
            float4 ghn = *(const float4*)(ghrow + 128 + c);
            float4 hv  = *(const float4*)(hin + (size_t)node * 64 + c);
            float4 bir = *(const float4*)(s_bias + c);
            float4 biz = *(const float4*)(s_bias + 64 + c);
            float4 bin = *(const float4*)(s_bias + 128 + c);
            float4 bhr = *(const float4*)(s_bias + 192 + c);
            float4 bhz = *(const float4*)(s_bias + 256 + c);
            float4 bhn = *(const float4*)(s_bias + 320 + c);
            float gr[4] = {gir.x + bir.x + ghr.x + bhr.x, gir.y + bir.y + ghr.y + bhr.y,
                           gir.z + bir.z + ghr.z + bhr.z, gir.w + bir.w + ghr.w + bhr.w};
            float gz[4] = {giz.x + biz.x + ghz.x + bhz.x, giz.y + biz.y + ghz.y + bhz.y,
                           giz.z + biz.z + ghz.z + bhz.z, giz.w + biz.w + ghz.w + bhz.w};
            float gni[4] = {gin.x + bin.x, gin.y + bin.y, gin.z + bin.z, gin.w + bin.w};
            float gnh[4] = {ghn.x + bhn.x, ghn.y + bhn.y, ghn.z + bhn.z, ghn.w + bhn.w};
            float hvv[4] = {hv.x, hv.y, hv.z, hv.w};
            float o_[4], lo_[4];
#pragma unroll
            for (int j = 0; j < 4; j++) {
                float rr = sigf(gr[j]);
                float zz = sigf(gz[j]);
                float nn = tanhf(gni[j] + rr * gnh[j]);
                o_[j] = (1.0f - zz) * nn + zz * hvv[j];
                __half hh = __float2half_rn(o_[j]);
                lo_[j] = o_[j] - __half2float(hh);
            }
            *(float4*)(hout + (size_t)node * 64 + c) = make_float4(o_[0], o_[1], o_[2], o_[3]);
            __half2* hsp = (__half2*)(g_hs + (size_t)node * 128 + c);
            hsp[0] = __floats2half2_rn(o_[0], o_[1]);
            hsp[1] = __floats2half2_rn(o_[2], o_[3]);
            __half2* lsp = (__half2*)(g_hs + (size_t)node * 128 + 64 + c);
            lsp[0] = __floats2half2_rn(lo_[0], lo_[1]);
            lsp[1] = __floats2half2_rn(lo_[2], lo_[3]);
        }
    }
}

// ---------------- decoder: tensorized, 128 edges/block ----------------
// smem (u32): A1 @0 (128*148=18944) | B1 @18944 (64*148=9472) -> 28416
//             misc @28416: w3(128) b1(64) b2(32) b3(4) -> 28644
//             A2/d1 @28672 (128*68=8704) -> 37376 | B2 @37376 (32*68=2176) -> 39552
//             d2 @39552 (128*36=4608) -> 44160
#define DEC_SMEM (44160 * 4)

__global__ __launch_bounds__(256) void decoder_kernel(int parity,
        const float* __restrict__ ea,
        const float* __restrict__ bd1, const float* __restrict__ bd2,
        const float* __restrict__ Wd3, const float* __restrict__ bd3,
        float* __restrict__ out) {
    const float* hin = parity ? g_h1 : g_h0;
    extern __shared__ uint32_t sw[];
    uint32_t* A1 = sw;                   // stride 148 (=296 halves)
    uint32_t* B1 = sw + 18944;           // stride 148
    float* s_w3  = (float*)(sw + 28416); // 128
    float* s_b1  = (float*)(sw + 28544); // 64
    float* s_b2  = (float*)(sw + 28608); // 32
    float* s_b3  = (float*)(sw + 28640); // 4
    uint32_t* A2 = sw + 28672;           // stride 68
    uint32_t* B2 = sw + 37376;           // stride 68
    float* s_d2  = (float*)(sw + 39552); // stride 36

    const int t = threadIdx.x;
    const int eb = blockIdx.x * 128;
    const int wid = t >> 5, lane = t & 31;
    const int wm = wid & 3, wn = wid >> 2;     // 4M x 2N
    const int g = lane >> 2, t4 = lane & 3;

    if (t < 128) s_w3[t] = Wd3[t];
    if (t < 64) s_b1[t] = bd1[t];
    if (t < 32) s_b2[t] = bd2[t];
    if (t < 4)  s_b3[t] = bd3[t];

    // stage B1 (64 x 288 halves = 64 x 144 u32) into stride-148 rows
    for (int i = t; i < 64 * 144; i += 256) {
        int row = i / 144, q = i % 144;
        B1[row * 148 + q] = ((const uint32_t*)g_d1s)[i];
    }
    // stage B2 (32 x 128 halves = 32 x 64 u32)
    for (int i = t; i < 32 * 64; i += 256) {
        int row = i >> 6, q = i & 63;
        B2[row * 68 + q] = ((const uint32_t*)g_d2s)[i];
    }
    // stage A1: e_in split. 2 threads/row; half=0 -> cols 0..71, half=1 -> 72..143
    {
        int r = t >> 1, half = t & 1;
        int e = eb + r;
        int s = g_src[e], d = g_dst[e];
        __half* arow = (__half*)(A1 + r * 148);
#pragma unroll
        for (int c = 0; c < 72; c++) {
            int col = half * 72 + c;
            float v;
            if (col < 64) v = hin[(size_t)s * H + col];
            else if (col < 128) v = hin[(size_t)d * H + col - 64];
            else if (col < 133) v = ea[(size_t)e * ED + col - 128];
            else v = 0.0f;
            __half hi = __float2half_rn(v);
            arow[col] = hi;
            arow[144 + col] = __float2half_rn(v - __half2float(hi));
        }
    }
    __syncthreads();

    // GEMM1: M=128, N=64, ks=18 (K=288 halves)
    float acc[2][4][4];
#pragma unroll
    for (int mi = 0; mi < 2; mi++)
#pragma unroll
        for (int ni = 0; ni < 4; ni++)
#pragma unroll
            for (int q = 0; q < 4; q++) acc[mi][ni][q] = 0.0f;
    {
        const uint32_t* Aw = A1 + (wm * 32 + g) * 148;
        const uint32_t* Bw = B1 + (wn * 32 + g) * 148;
#pragma unroll
        for (int ks = 0; ks < 18; ks++) {
            const int idx0 = ks * 8 + t4;
            uint32_t a[2][4], b[4][2];
#pragma unroll
            for (int mi = 0; mi < 2; mi++) {
                const uint32_t* p = Aw + mi * 16 * 148;
                a[mi][0] = p[idx0];
                a[mi][1] = p[8 * 148 + idx0];
                a[mi][2] = p[idx0 + 4];
                a[mi][3] = p[8 * 148 + idx0 + 4];
            }
#pragma unroll
            for (int ni = 0; ni < 4; ni++) {
                const uint32_t* p = Bw + ni * 8 * 148;
                b[ni][0] = p[idx0];
                b[ni][1] = p[idx0 + 4];
            }
#pragma unroll
            for (int mi = 0; mi < 2; mi++)
#pragma unroll
                for (int ni = 0; ni < 4; ni++)
                    mma16816(acc[mi][ni], a[mi], b[ni]);
        }
    }
    // d1 = relu(acc + b1) -> split into A2 (disjoint region, no sync needed before writes)
#pragma unroll
    for (int ni = 0; ni < 4; ni++) {
        int col = wn * 32 + ni * 8 + 2 * t4;
        float b0 = s_b1[col], b1v = s_b1[col + 1];
#pragma unroll
        for (int mi = 0; mi < 2; mi++) {
            int row = wm * 32 + mi * 16 + g;
#pragma unroll
            for (int hrow = 0; hrow < 2; hrow++) {
                int rr = row + hrow * 8;
                float v0 = fmaxf(acc[mi][ni][hrow * 2 + 0] + b0, 0.0f);
                float v1 = fmaxf(acc[mi][ni][hrow * 2 + 1] + b1v, 0.0f);
                __half h0 = __float2half_rn(v0), h1 = __float2half_rn(v1);
                __half2 hi = __halves2half2(h0, h1);
                __half2 lo = __halves2half2(__float2half_rn(v0 - __half2float(h0)),
                                            __float2half_rn(v1 - __half2float(h1)));
                A2[rr * 68 + col / 2] = *(uint32_t*)&hi;
                A2[rr * 68 + 32 + col / 2] = *(uint32_t*)&lo;
            }
        }
    }
    __syncthreads();

    // GEMM2: M=128, N=32, ks=8 (K=128 halves)
    float acc2[2][2][4];
#pragma unroll
    for (int mi = 0; mi < 2; mi++)
#pragma unroll
        for (int ni = 0; ni < 2; ni++)
#pragma unroll
            for (int q = 0; q < 4; q++) acc2[mi][ni][q] = 0.0f;
    {
        const uint32_t* Aw = A2 + (wm * 32 + g) * 68;
        const uint32_t* Bw = B2 + (wn * 16 + g) * 68;
#pragma unroll
        for (int ks = 0; ks < 8; ks++) {
            const int idx0 = ks * 8 + t4;
            uint32_t a[2][4], b[2][2];
#pragma unroll
            for (int mi = 0; mi < 2; mi++) {
                const uint32_t* p = Aw + mi * 16 * 68;
                a[mi][0] = p[idx0];
                a[mi][1] = p[8 * 68 + idx0];
                a[mi][2] = p[idx0 + 4];
                a[mi][3] = p[8 * 68 + idx0 + 4];
            }
#pragma unroll
            for (int ni = 0; ni < 2; ni++) {
                const uint32_t* p = Bw + ni * 8 * 68;
                b[ni][0] = p[idx0];
                b[ni][1] = p[idx0 + 4];
            }
#pragma unroll
            for (int mi = 0; mi < 2; mi++)
#pragma unroll
                for (int ni = 0; ni < 2; ni++)
                    mma16816(acc2[mi][ni], a[mi], b[ni]);
        }
    }
    // d2 = relu(acc2 + b2) -> s_d2 (disjoint region)
#pragma unroll
    for (int ni = 0; ni < 2; ni++) {
        int col = wn * 16 + ni * 8 + 2 * t4;
        float b0 = s_b2[col], b1v = s_b2[col + 1];
#pragma unroll
        for (int mi = 0; mi < 2; mi++) {
            int row = wm * 32 + mi * 16 + g;
            *(float2*)(s_d2 + row * 36 + col) =
                make_float2(fmaxf(acc2[mi][ni][0] + b0, 0.0f), fmaxf(acc2[mi][ni][1] + b1v, 0.0f));
            *(float2*)(s_d2 + (row + 8) * 36 + col) =
                make_float2(fmaxf(acc2[mi][ni][2] + b0, 0.0f), fmaxf(acc2[mi][ni][3] + b1v, 0.0f));
        }
    }
    __syncthreads();

    // layer3: 2 threads/row, each 2 outputs (32 MACs each)
    {
        int r = t >> 1, half = t & 1;
        int e = eb + r;
        const float* drow = s_d2 + r * 36;
        float a0 = s_b3[half * 2], a1 = s_b3[half * 2 + 1];
        const float* w0 = s_w3 + (half * 2) * 32;
        const float* w1 = w0 + 32;
#pragma unroll
        for (int j = 0; j < 32; j++) {
            float v = drow[j];
            a0 += v * w0[j];
            a1 += v * w1[j];
        }
        *(float2*)(out + (size_t)e * T_OUT + half * 2) = make_float2(a0, a1);
    }
}

static void set_attrs() {
    cudaFuncSetAttribute(ewgemm_kernel, cudaFuncAttributeMaxDynamicSharedMemorySize, GEMM_SMEM);
    cudaFuncSetAttribute(gru_fused_kernel, cudaFuncAttributeMaxDynamicSharedMemorySize, GRU_SMEM);
    cudaFuncSetAttribute(decoder_kernel, cudaFuncAttributeMaxDynamicSharedMemorySize, DEC_SMEM);
}

namespace { struct WarmLoad { WarmLoad() { set_attrs(); } } s_warm; }

extern "C" void kernel_launch(void* const* d_in, const int* in_sizes, int n_in,
                              void* d_out, int out_size) {
    (void)in_sizes; (void)n_in; (void)out_size;
    const float* x   = (const float*)d_in[0];
    const void*  ei  = d_in[1];
    const float* ea  = (const float*)d_in[2];
    const float* u   = (const float*)d_in[3];
    const float* Wp  = (const float*)d_in[4];
    const float* bp  = (const float*)d_in[5];
    const float* We1 = (const float*)d_in[6];
    const float* be1 = (const float*)d_in[7];
    const float* We2 = (const float*)d_in[8];
    const float* be2 = (const float*)d_in[9];
    const float* root = (const float*)d_in[10];
    const float* cb   = (const float*)d_in[11];
    const float* Wih = (const float*)d_in[12];
    const float* bih = (const float*)d_in[13];
    const float* Whh = (const float*)d_in[14];
    const float* bhh = (const float*)d_in[15];
    const float* Wd1 = (const float*)d_in[16];
    const float* bd1 = (const float*)d_in[17];
    const float* Wd2 = (const float*)d_in[18];
    const float* bd2 = (const float*)d_in[19];
    const float* Wd3 = (const float*)d_in[20];
    const float* bd3 = (const float*)d_in[21];
    float* out = (float*)d_out;

    set_attrs();

    init_kernel<<<N_NODES * H / 4 / 256, 256>>>((const long long*)ei, Whh, root, Wih, Wd1, Wd2, We2);
    conv_count_kernel<<<N_EDGES / 256, 256>>>(ei);
    hinit_kernel<<<N_NODES / 16, 256>>>(x, u, Wp, bp);
    rfeat_kernel<<<N_EDGES / 16, 256>>>(ea, We1, be1);

    {
        dim3 grid(4096 / 128, N_EDGES / 128);
        ewgemm_kernel<<<grid, 256, GEMM_SMEM>>>(be2);
    }

    for (int s = 0; s < STEPS; s++) {
        int parity = s & 1;
        msg_kernel<<<N_EDGES / 16, 512>>>(parity);
        gru_fused_kernel<<<N_NODES / 128, 512, GRU_SMEM>>>(parity, bih, bhh, cb);
    }

    decoder_kernel<<<N_EDGES / 128, 256, DEC_SMEM>>>(1, ea, bd1, bd2, Wd3, bd3, out);
}